// round 11
// baseline (speedup 1.0000x reference)
#include <cuda_runtime.h>
#include <cstdint>

#define MAX_SAMPLES 512
#define THREADS 1024
#define RPW 8                      // rounds per window
#define ROUND_PTS (THREADS * 4)    // 4096 contiguous, coalesced points/round
#define WIN (RPW * ROUND_PTS)      // 32768 (fill point +10.7 sigma)

// Match XLA's non-contracted, left-associated ((x*x)+(y*y))+(z*z).
__device__ __forceinline__ unsigned octant_of(float x, float y, float z) {
    float r2 = __fadd_rn(__fadd_rn(__fmul_rn(x, x), __fmul_rn(y, y)), __fmul_rn(z, z));
    if (!(r2 <= 1.0f)) return 0xFu;                       // invalid marker
    return ((x >= 0.0f) ? 4u : 0u) | ((y >= 0.0f) ? 2u : 0u) | ((z >= 0.0f) ? 1u : 0u);
}

// One block per batch. Window = 8 rounds x 4096 contiguous points; thread t
// owns points [r0 + 4t, 4t+4) each round -> perfectly coalesced float4 loads
// AND thread order == index order within a round. Per-round packed scan gives
// ordered ranks with 3 barriers/round.
__global__ __launch_bounds__(THREADS, 1)
void octant_query_fused(const float* __restrict__ pcs, float* __restrict__ out, int N) {
    const int b    = blockIdx.x;
    const int tid  = threadIdx.x;
    const int lane = tid & 31;
    const int w    = tid >> 5;

    const float* __restrict__ xs = pcs + (size_t)b * 3 * N;
    const float* __restrict__ ys = xs + N;
    const float* __restrict__ zs = ys + N;
    float* __restrict__ out_b = out + (size_t)b * (8 * MAX_SAMPLES);

    __shared__ unsigned sm_ws[32][2];    // per-warp packed-8 sums
    __shared__ unsigned sm_off[32][4];   // per-warp packed-16 exclusive offsets
    __shared__ unsigned sh_totw[4];      // round totals, packed-16
    __shared__ int sh_gbase[8];          // running global base per octant

    if (tid < 8) sh_gbase[tid] = 0;
    __syncthreads();

    bool allfull = false;

    for (int win = 0; win < N && !allfull; win += WIN) {
        // ---- Phase 1: coalesced loads, classify all 8 rounds up front ----
        unsigned pk[RPW];                // 4 nibbles/round: octant or 0xF
#pragma unroll
        for (int r = 0; r < RPW; r++) {
            const int i = win + r * ROUND_PTS + tid * 4;
            float px[4], py[4], pz[4];
            if (i + 3 < N) {
                const float4 vx = *reinterpret_cast<const float4*>(xs + i);
                const float4 vy = *reinterpret_cast<const float4*>(ys + i);
                const float4 vz = *reinterpret_cast<const float4*>(zs + i);
                px[0] = vx.x; px[1] = vx.y; px[2] = vx.z; px[3] = vx.w;
                py[0] = vy.x; py[1] = vy.y; py[2] = vy.z; py[3] = vy.w;
                pz[0] = vz.x; pz[1] = vz.y; pz[2] = vz.z; pz[3] = vz.w;
            } else {
#pragma unroll
                for (int j = 0; j < 4; j++) {
                    const int ii = i + j;
                    const bool ok = (ii < N);
                    px[j] = ok ? xs[ii] : 2.0f;   // sentinel: outside ball
                    py[j] = ok ? ys[ii] : 2.0f;
                    pz[j] = ok ? zs[ii] : 2.0f;
                }
            }
            unsigned word = 0;
#pragma unroll
            for (int j = 0; j < 4; j++)
                word |= octant_of(px[j], py[j], pz[j]) << (4 * j);
            pk[r] = word;
        }

        // ---- Phase 2: per-round ordered rank + write ----
#pragma unroll 1
        for (int r = 0; r < RPW; r++) {
            if (allfull) break;
            const unsigned word = pk[r];

            // count (packed 8-bit x 8) + per-point local rank (2 bits)
            unsigned clo = 0, chi = 0, lrp = 0;
#pragma unroll
            for (int j = 0; j < 4; j++) {
                const unsigned o = (word >> (4 * j)) & 0xFu;
                if (o < 8u) {
                    const unsigned sh  = 8u * (o & 3u);
                    const unsigned cur = (o < 4u) ? clo : chi;
                    lrp |= ((cur >> sh) & 3u) << (2 * j);
                    if (o < 4u) clo += 1u << sh; else chi += 1u << sh;
                }
            }

            // warp inclusive scan (packed 8-bit; warp sums <= 128)
            unsigned slo = clo, shi = chi;
#pragma unroll
            for (int d = 1; d < 32; d <<= 1) {
                const unsigned tlo = __shfl_up_sync(0xFFFFFFFFu, slo, d);
                const unsigned thi = __shfl_up_sync(0xFFFFFFFFu, shi, d);
                if (lane >= d) { slo += tlo; shi += thi; }
            }
            if (lane == 31) { sm_ws[w][0] = slo; sm_ws[w][1] = shi; }
            __syncthreads();                                   // (A)

            // warp 0: expand to 16-bit, scan the 32 warp sums
            if (w == 0) {
                const unsigned alo = sm_ws[lane][0], ahi = sm_ws[lane][1];
                unsigned t0 = (alo & 0xFFu)         | (((alo >> 8)  & 0xFFu) << 16);
                unsigned t1 = ((alo >> 16) & 0xFFu) | (((alo >> 24) & 0xFFu) << 16);
                unsigned t2 = (ahi & 0xFFu)         | (((ahi >> 8)  & 0xFFu) << 16);
                unsigned t3 = ((ahi >> 16) & 0xFFu) | (((ahi >> 24) & 0xFFu) << 16);
                const unsigned o0 = t0, o1 = t1, o2 = t2, o3 = t3;
#pragma unroll
                for (int d = 1; d < 32; d <<= 1) {
                    const unsigned u0 = __shfl_up_sync(0xFFFFFFFFu, t0, d);
                    const unsigned u1 = __shfl_up_sync(0xFFFFFFFFu, t1, d);
                    const unsigned u2 = __shfl_up_sync(0xFFFFFFFFu, t2, d);
                    const unsigned u3 = __shfl_up_sync(0xFFFFFFFFu, t3, d);
                    if (lane >= d) { t0 += u0; t1 += u1; t2 += u2; t3 += u3; }
                }
                sm_off[lane][0] = t0 - o0; sm_off[lane][1] = t1 - o1;
                sm_off[lane][2] = t2 - o2; sm_off[lane][3] = t3 - o3;
                if (lane == 31) {
                    sh_totw[0] = t0; sh_totw[1] = t1; sh_totw[2] = t2; sh_totw[3] = t3;
                }
            }
            __syncthreads();                                   // (B)

            // assemble per-thread bases; uniform full-check for next round
            const unsigned elo = slo - clo, ehi = shi - chi;   // thread-excl (8-bit)
            const unsigned f0 = sm_off[w][0], f1 = sm_off[w][1];
            const unsigned f2 = sm_off[w][2], f3 = sm_off[w][3];
            const unsigned g0 = sh_totw[0], g1 = sh_totw[1];
            const unsigned g2 = sh_totw[2], g3 = sh_totw[3];

            int base[8], tot[8];
            base[0] = sh_gbase[0] + (int)(f0 & 0xFFFFu) + (int)(elo & 0xFFu);
            base[1] = sh_gbase[1] + (int)(f0 >> 16)     + (int)((elo >> 8)  & 0xFFu);
            base[2] = sh_gbase[2] + (int)(f1 & 0xFFFFu) + (int)((elo >> 16) & 0xFFu);
            base[3] = sh_gbase[3] + (int)(f1 >> 16)     + (int)(elo >> 24);
            base[4] = sh_gbase[4] + (int)(f2 & 0xFFFFu) + (int)(ehi & 0xFFu);
            base[5] = sh_gbase[5] + (int)(f2 >> 16)     + (int)((ehi >> 8)  & 0xFFu);
            base[6] = sh_gbase[6] + (int)(f3 & 0xFFFFu) + (int)((ehi >> 16) & 0xFFu);
            base[7] = sh_gbase[7] + (int)(f3 >> 16)     + (int)(ehi >> 24);
            tot[0] = (int)(g0 & 0xFFFFu); tot[1] = (int)(g0 >> 16);
            tot[2] = (int)(g1 & 0xFFFFu); tot[3] = (int)(g1 >> 16);
            tot[4] = (int)(g2 & 0xFFFFu); tot[5] = (int)(g2 >> 16);
            tot[6] = (int)(g3 & 0xFFFFu); tot[7] = (int)(g3 >> 16);

            bool nf = true;
#pragma unroll
            for (int q = 0; q < 8; q++)
                nf = nf && (sh_gbase[q] + tot[q] >= MAX_SAMPLES);
            __syncthreads();                                   // (C)

            if (tid < 8) sh_gbase[tid] += tot[tid];
            allfull = nf;                                      // uniform

            // ordered writes (independent; base is pre-update snapshot)
#pragma unroll
            for (int j = 0; j < 4; j++) {
                const unsigned o = (word >> (4 * j)) & 0xFu;
                if (o < 8u) {
                    const int rk = base[o] + (int)((lrp >> (2 * j)) & 3u);
                    if (rk < MAX_SAMPLES)
                        out_b[((int)o << 9) + rk] =
                            (float)(win + r * ROUND_PTS + tid * 4 + j);
                }
            }
        }
    }

    // ---- fill unwritten tail slots with DEFAULT (-1) ----
    __syncthreads();
#pragma unroll
    for (int j = 0; j < (8 * MAX_SAMPLES) / THREADS; j++) {
        const int s = j * THREADS + tid;
        const int q = s >> 9;
        const int rk = s & (MAX_SAMPLES - 1);
        if (rk >= sh_gbase[q]) out_b[s] = -1.0f;
    }
}

extern "C" void kernel_launch(void* const* d_in, const int* in_sizes, int n_in,
                              void* d_out, int out_size) {
    const float* pcs = (const float*)d_in[0];
    float* out = (float*)d_out;

    int B = out_size / (8 * MAX_SAMPLES);   // 16
    if (B < 1) B = 1;
    if (B > 64) B = 64;
    int N = in_sizes[0] / (3 * B);          // 200000

    octant_query_fused<<<B, THREADS>>>(pcs, out, N);
}

// round 12
// speedup vs baseline: 1.0169x; 1.0169x over previous
#include <cuda_runtime.h>
#include <cstdint>

#define MAX_SAMPLES 512
#define TPB_A 128
#define CHUNK_A 512
#define KC 64                        // chunks per batch (fixed window coverage)
#define W (KC * CHUNK_A)             // 32768-pt window (fill pt +10.7 sigma)
#define CODES_PER_B (W / 4)          // 8192 ushorts per batch
#define THREADS_B 1024
#define ROUND_PTS 4096               // points per ordered round in write kernel
#define MAXB 64

__device__ unsigned short g_codes[MAXB * CODES_PER_B];   // 1 MB scratch

// Match XLA's non-contracted, left-associated ((x*x)+(y*y))+(z*z).
__device__ __forceinline__ unsigned octant_of(float x, float y, float z) {
    float r2 = __fadd_rn(__fadd_rn(__fmul_rn(x, x), __fmul_rn(y, y)), __fmul_rn(z, z));
    if (!(r2 <= 1.0f)) return 0xFu;
    return ((x >= 0.0f) ? 4u : 0u) | ((y >= 0.0f) ? 2u : 0u) | ((z >= 0.0f) ? 1u : 0u);
}

// ---------------------------------------------------------------------------
// Pass 1: stream the window with ~1024 blocks; emit 4-bit octant codes and
// blanket-fill the output with -1. Pure streaming, no atomics/smem.
// ---------------------------------------------------------------------------
__global__ void classify_kernel(const float* __restrict__ pcs, float* __restrict__ out,
                                int N, int out_count) {
    const int b   = blockIdx.x >> 6;      // / KC
    const int k   = blockIdx.x & (KC - 1);
    const int tid = threadIdx.x;

    // Output fill: grid has B*KC*TPB_A = B*8192 threads >= out_count = B*4096.
    const int fidx = blockIdx.x * TPB_A + tid;
    if (fidx < out_count) out[fidx] = -1.0f;

    const int i0 = k * CHUNK_A + tid * 4;
    unsigned word = 0xFFFFu;              // all-invalid (pad)
    if (i0 < N) {
        const float* __restrict__ xs = pcs + (size_t)b * 3 * N;
        const float* __restrict__ ys = xs + N;
        const float* __restrict__ zs = ys + N;
        float px[4], py[4], pz[4];
        if (i0 + 3 < N && (N & 3) == 0) {
            const float4 vx = *reinterpret_cast<const float4*>(xs + i0);
            const float4 vy = *reinterpret_cast<const float4*>(ys + i0);
            const float4 vz = *reinterpret_cast<const float4*>(zs + i0);
            px[0] = vx.x; px[1] = vx.y; px[2] = vx.z; px[3] = vx.w;
            py[0] = vy.x; py[1] = vy.y; py[2] = vy.z; py[3] = vy.w;
            pz[0] = vz.x; pz[1] = vz.y; pz[2] = vz.z; pz[3] = vz.w;
        } else {
#pragma unroll
            for (int j = 0; j < 4; j++) {
                const int ii = i0 + j;
                const bool ok = (ii < N);
                px[j] = ok ? xs[ii] : 2.0f;   // sentinel: outside ball
                py[j] = ok ? ys[ii] : 2.0f;
                pz[j] = ok ? zs[ii] : 2.0f;
            }
        }
        word = 0;
#pragma unroll
        for (int j = 0; j < 4; j++)
            word |= octant_of(px[j], py[j], pz[j]) << (4 * j);
    }
    g_codes[b * CODES_PER_B + (i0 >> 2)] = (unsigned short)word;
}

// ---------------------------------------------------------------------------
// Pass 2: one block per batch; ordered ranks from the compact code array
// (16 KB/batch). Per-round packed scan, 3 barriers/round, early exit.
// Rounds beyond the code window fall back to raw float loads (correctness).
// ---------------------------------------------------------------------------
__global__ __launch_bounds__(THREADS_B, 1)
void write_kernel(const float* __restrict__ pcs, float* __restrict__ out, int N) {
    const int b    = blockIdx.x;
    const int tid  = threadIdx.x;
    const int lane = tid & 31;
    const int w    = tid >> 5;

    const float* __restrict__ xs = pcs + (size_t)b * 3 * N;
    const float* __restrict__ ys = xs + N;
    const float* __restrict__ zs = ys + N;
    float* __restrict__ out_b = out + (size_t)b * (8 * MAX_SAMPLES);
    const unsigned short* __restrict__ cp = g_codes + b * CODES_PER_B;

    __shared__ unsigned sm_ws[32][2];
    __shared__ unsigned sm_off[32][4];
    __shared__ unsigned sh_totw[4];
    __shared__ int sh_gbase[8];

    if (tid < 8) sh_gbase[tid] = 0;

    // Prefetch all 8 window rounds' codes (coalesced; overlapped latency).
    unsigned pk[W / ROUND_PTS];
#pragma unroll
    for (int r = 0; r < W / ROUND_PTS; r++)
        pk[r] = cp[r * THREADS_B + tid];
    __syncthreads();

    const int nrounds = (N + ROUND_PTS - 1) / ROUND_PTS;
    bool allfull = false;

    for (int r = 0; r < nrounds && !allfull; r++) {
        unsigned word;
        if (r < W / ROUND_PTS) {
            word = pk[r];
        } else {
            // raw fallback beyond the code window (benchmark never reaches it)
            const int i = r * ROUND_PTS + tid * 4;
            float px[4], py[4], pz[4];
            if (i + 3 < N && (N & 3) == 0) {
                const float4 vx = *reinterpret_cast<const float4*>(xs + i);
                const float4 vy = *reinterpret_cast<const float4*>(ys + i);
                const float4 vz = *reinterpret_cast<const float4*>(zs + i);
                px[0] = vx.x; px[1] = vx.y; px[2] = vx.z; px[3] = vx.w;
                py[0] = vy.x; py[1] = vy.y; py[2] = vy.z; py[3] = vy.w;
                pz[0] = vz.x; pz[1] = vz.y; pz[2] = vz.z; pz[3] = vz.w;
            } else {
#pragma unroll
                for (int j = 0; j < 4; j++) {
                    const int ii = i + j;
                    const bool ok = (ii < N);
                    px[j] = ok ? xs[ii] : 2.0f;
                    py[j] = ok ? ys[ii] : 2.0f;
                    pz[j] = ok ? zs[ii] : 2.0f;
                }
            }
            word = 0;
#pragma unroll
            for (int j = 0; j < 4; j++)
                word |= octant_of(px[j], py[j], pz[j]) << (4 * j);
        }

        // per-thread counts (packed 8-bit x8) + local ranks (2 bits/pt)
        unsigned clo = 0, chi = 0, lrp = 0;
#pragma unroll
        for (int j = 0; j < 4; j++) {
            const unsigned o = (word >> (4 * j)) & 0xFu;
            if (o < 8u) {
                const unsigned sh  = 8u * (o & 3u);
                const unsigned cur = (o < 4u) ? clo : chi;
                lrp |= ((cur >> sh) & 3u) << (2 * j);
                if (o < 4u) clo += 1u << sh; else chi += 1u << sh;
            }
        }

        // warp inclusive scan (packed 8-bit; warp sums <= 128)
        unsigned slo = clo, shi = chi;
#pragma unroll
        for (int d = 1; d < 32; d <<= 1) {
            const unsigned tlo = __shfl_up_sync(0xFFFFFFFFu, slo, d);
            const unsigned thi = __shfl_up_sync(0xFFFFFFFFu, shi, d);
            if (lane >= d) { slo += tlo; shi += thi; }
        }
        if (lane == 31) { sm_ws[w][0] = slo; sm_ws[w][1] = shi; }
        __syncthreads();                                   // (A)

        if (w == 0) {
            const unsigned alo = sm_ws[lane][0], ahi = sm_ws[lane][1];
            unsigned t0 = (alo & 0xFFu)         | (((alo >> 8)  & 0xFFu) << 16);
            unsigned t1 = ((alo >> 16) & 0xFFu) | (((alo >> 24) & 0xFFu) << 16);
            unsigned t2 = (ahi & 0xFFu)         | (((ahi >> 8)  & 0xFFu) << 16);
            unsigned t3 = ((ahi >> 16) & 0xFFu) | (((ahi >> 24) & 0xFFu) << 16);
            const unsigned o0 = t0, o1 = t1, o2 = t2, o3 = t3;
#pragma unroll
            for (int d = 1; d < 32; d <<= 1) {
                const unsigned u0 = __shfl_up_sync(0xFFFFFFFFu, t0, d);
                const unsigned u1 = __shfl_up_sync(0xFFFFFFFFu, t1, d);
                const unsigned u2 = __shfl_up_sync(0xFFFFFFFFu, t2, d);
                const unsigned u3 = __shfl_up_sync(0xFFFFFFFFu, t3, d);
                if (lane >= d) { t0 += u0; t1 += u1; t2 += u2; t3 += u3; }
            }
            sm_off[lane][0] = t0 - o0; sm_off[lane][1] = t1 - o1;
            sm_off[lane][2] = t2 - o2; sm_off[lane][3] = t3 - o3;
            if (lane == 31) {
                sh_totw[0] = t0; sh_totw[1] = t1; sh_totw[2] = t2; sh_totw[3] = t3;
            }
        }
        __syncthreads();                                   // (B)

        const unsigned elo = slo - clo, ehi = shi - chi;
        const unsigned f0 = sm_off[w][0], f1 = sm_off[w][1];
        const unsigned f2 = sm_off[w][2], f3 = sm_off[w][3];
        const unsigned g0 = sh_totw[0], g1 = sh_totw[1];
        const unsigned g2 = sh_totw[2], g3 = sh_totw[3];

        int base[8], tot[8];
        base[0] = sh_gbase[0] + (int)(f0 & 0xFFFFu) + (int)(elo & 0xFFu);
        base[1] = sh_gbase[1] + (int)(f0 >> 16)     + (int)((elo >> 8)  & 0xFFu);
        base[2] = sh_gbase[2] + (int)(f1 & 0xFFFFu) + (int)((elo >> 16) & 0xFFu);
        base[3] = sh_gbase[3] + (int)(f1 >> 16)     + (int)(elo >> 24);
        base[4] = sh_gbase[4] + (int)(f2 & 0xFFFFu) + (int)(ehi & 0xFFu);
        base[5] = sh_gbase[5] + (int)(f2 >> 16)     + (int)((ehi >> 8)  & 0xFFu);
        base[6] = sh_gbase[6] + (int)(f3 & 0xFFFFu) + (int)((ehi >> 16) & 0xFFu);
        base[7] = sh_gbase[7] + (int)(f3 >> 16)     + (int)(ehi >> 24);
        tot[0] = (int)(g0 & 0xFFFFu); tot[1] = (int)(g0 >> 16);
        tot[2] = (int)(g1 & 0xFFFFu); tot[3] = (int)(g1 >> 16);
        tot[4] = (int)(g2 & 0xFFFFu); tot[5] = (int)(g2 >> 16);
        tot[6] = (int)(g3 & 0xFFFFu); tot[7] = (int)(g3 >> 16);

        bool nf = true;
#pragma unroll
        for (int q = 0; q < 8; q++)
            nf = nf && (sh_gbase[q] + tot[q] >= MAX_SAMPLES);
        __syncthreads();                                   // (C)

        if (tid < 8) sh_gbase[tid] += tot[tid];
        allfull = nf;                                      // uniform

        // ordered writes (base = pre-update snapshot; thread order = index order)
#pragma unroll
        for (int j = 0; j < 4; j++) {
            const unsigned o = (word >> (4 * j)) & 0xFu;
            if (o < 8u) {
                const int rk = base[o] + (int)((lrp >> (2 * j)) & 3u);
                if (rk < MAX_SAMPLES)
                    out_b[((int)o << 9) + rk] = (float)(r * ROUND_PTS + tid * 4 + j);
            }
        }
    }
    // tail slots already hold -1 from classify_kernel's fill
}

// ---------------------------------------------------------------------------
extern "C" void kernel_launch(void* const* d_in, const int* in_sizes, int n_in,
                              void* d_out, int out_size) {
    const float* pcs = (const float*)d_in[0];
    float* out = (float*)d_out;

    int B = out_size / (8 * MAX_SAMPLES);   // 16
    if (B < 1) B = 1;
    if (B > MAXB) B = MAXB;
    int N = in_sizes[0] / (3 * B);          // 200000

    classify_kernel<<<B * KC, TPB_A>>>(pcs, out, N, B * 8 * MAX_SAMPLES);
    write_kernel<<<B, THREADS_B>>>(pcs, out, N);
}

// round 13
// speedup vs baseline: 2.0995x; 2.0645x over previous
#include <cuda_runtime.h>
#include <cstdint>

#define MAX_SAMPLES 512
#define TPB_A 128
#define CHUNK_A 512
#define KC 64                        // chunks per batch window
#define W (KC * CHUNK_A)             // 32768-pt window (fill pt +10.7 sigma)
#define CODES_PER_B (W / 4)          // 8192 ushorts per batch
#define SEGS 8
#define SEG_PTS (W / SEGS)           // 4096
#define CHUNKS_PER_SEG (SEG_PTS / CHUNK_A)   // 8
#define THREADS_B 1024
#define MAXB 64

__device__ unsigned short g_codes[MAXB * CODES_PER_B];   // 1 MB
__device__ int g_counts[MAXB * KC * 8];                  // 128 KB

// Match XLA's non-contracted, left-associated ((x*x)+(y*y))+(z*z).
__device__ __forceinline__ unsigned octant_of(float x, float y, float z) {
    float r2 = __fadd_rn(__fadd_rn(__fmul_rn(x, x), __fmul_rn(y, y)), __fmul_rn(z, z));
    if (!(r2 <= 1.0f)) return 0xFu;
    return ((x >= 0.0f) ? 4u : 0u) | ((y >= 0.0f) ? 2u : 0u) | ((z >= 0.0f) ? 1u : 0u);
}

// ---------------------------------------------------------------------------
// Pass 1 (wide): classify window points -> 4-bit codes, per-chunk octant
// counts, and blanket -1 output fill. 1024 blocks for 16 batches.
// ---------------------------------------------------------------------------
__global__ void classify_kernel(const float* __restrict__ pcs, float* __restrict__ out,
                                int N, int out_count) {
    const int b   = blockIdx.x >> 6;      // / KC
    const int k   = blockIdx.x & (KC - 1);
    const int tid = threadIdx.x;

    const int fidx = blockIdx.x * TPB_A + tid;   // grid covers 2x out_count
    if (fidx < out_count) out[fidx] = -1.0f;

    const int i0 = k * CHUNK_A + tid * 4;
    unsigned word = 0xFFFFu;              // all-invalid (pad)
    if (i0 < N) {
        const float* __restrict__ xs = pcs + (size_t)b * 3 * N;
        const float* __restrict__ ys = xs + N;
        const float* __restrict__ zs = ys + N;
        float px[4], py[4], pz[4];
        if (i0 + 3 < N && (N & 3) == 0) {
            const float4 vx = *reinterpret_cast<const float4*>(xs + i0);
            const float4 vy = *reinterpret_cast<const float4*>(ys + i0);
            const float4 vz = *reinterpret_cast<const float4*>(zs + i0);
            px[0] = vx.x; px[1] = vx.y; px[2] = vx.z; px[3] = vx.w;
            py[0] = vy.x; py[1] = vy.y; py[2] = vy.z; py[3] = vy.w;
            pz[0] = vz.x; pz[1] = vz.y; pz[2] = vz.z; pz[3] = vz.w;
        } else {
#pragma unroll
            for (int j = 0; j < 4; j++) {
                const int ii = i0 + j;
                const bool ok = (ii < N);
                px[j] = ok ? xs[ii] : 2.0f;   // sentinel: outside ball
                py[j] = ok ? ys[ii] : 2.0f;
                pz[j] = ok ? zs[ii] : 2.0f;
            }
        }
        word = 0;
#pragma unroll
        for (int j = 0; j < 4; j++)
            word |= octant_of(px[j], py[j], pz[j]) << (4 * j);
    }
    g_codes[b * CODES_PER_B + (i0 >> 2)] = (unsigned short)word;

    // per-chunk counts (packed bytes -> warp reduce -> 4-warp combine)
    unsigned clo = 0, chi = 0;
#pragma unroll
    for (int j = 0; j < 4; j++) {
        const unsigned o = (word >> (4 * j)) & 0xFu;
        if (o < 8u) { if (o < 4u) clo += 1u << (8 * o); else chi += 1u << (8 * (o - 4)); }
    }
#pragma unroll
    for (int off = 16; off > 0; off >>= 1) {
        clo += __shfl_down_sync(0xFFFFFFFFu, clo, off);
        chi += __shfl_down_sync(0xFFFFFFFFu, chi, off);
    }
    __shared__ unsigned smc[4][2];
    if ((tid & 31) == 0) { smc[tid >> 5][0] = clo; smc[tid >> 5][1] = chi; }
    __syncthreads();
    if (tid < 8) {
        int v = 0;
#pragma unroll
        for (int w2 = 0; w2 < 4; w2++) {
            const unsigned c = (tid < 4) ? smc[w2][0] : smc[w2][1];
            v += (int)((c >> (8 * (tid & 3))) & 0xFFu);
        }
        g_counts[((size_t)b * KC + k) * 8 + tid] = v;
    }
}

// ---------------------------------------------------------------------------
// Pass 2 (wide): one block per 4096-pt segment (B*8 blocks). Exact bases from
// chunk counts; full segments exit before reading codes; active segments do a
// single packed-scan round. Last segment carries the (normally-skipped) tail.
// ---------------------------------------------------------------------------
__global__ __launch_bounds__(THREADS_B, 1)
void write_kernel(const float* __restrict__ pcs, float* __restrict__ out, int N) {
    const int b    = blockIdx.x / SEGS;
    const int seg  = blockIdx.x % SEGS;
    const int tid  = threadIdx.x;
    const int lane = tid & 31;
    const int w    = tid >> 5;

    __shared__ unsigned sm_ws[32][2];
    __shared__ unsigned sm_off[32][4];
    __shared__ unsigned sh_totw[4];
    __shared__ int sh_gbase[8];

    if (tid < 8) {
        int s = 0;
        const int kend = seg * CHUNKS_PER_SEG;
#pragma unroll 8
        for (int kk = 0; kk < kend; kk++)
            s += g_counts[((size_t)b * KC + kk) * 8 + tid];
        sh_gbase[tid] = s;
    }
    __syncthreads();

    {
        bool full = true;
#pragma unroll
        for (int q = 0; q < 8; q++) full = full && (sh_gbase[q] >= MAX_SAMPLES);
        if (full) return;                 // uniform; no code/point reads
    }

    const float* __restrict__ xs = pcs + (size_t)b * 3 * N;
    const float* __restrict__ ys = xs + N;
    const float* __restrict__ zs = ys + N;
    float* __restrict__ out_b = out + (size_t)b * (8 * MAX_SAMPLES);
    const unsigned short* __restrict__ cp = g_codes + b * CODES_PER_B;

    const bool last = (seg == SEGS - 1);

    for (int iter = 0; ; iter++) {
        int pbase;
        unsigned word;
        if (iter == 0) {
            pbase = seg * SEG_PTS;
            word = cp[seg * (SEG_PTS / 4) + tid];
        } else {
            pbase = W + (iter - 1) * SEG_PTS;        // raw tail (last block only)
            if (pbase >= N) break;
            const int i = pbase + tid * 4;
            float px[4], py[4], pz[4];
            if (i + 3 < N && (N & 3) == 0) {
                const float4 vx = *reinterpret_cast<const float4*>(xs + i);
                const float4 vy = *reinterpret_cast<const float4*>(ys + i);
                const float4 vz = *reinterpret_cast<const float4*>(zs + i);
                px[0] = vx.x; px[1] = vx.y; px[2] = vx.z; px[3] = vx.w;
                py[0] = vy.x; py[1] = vy.y; py[2] = vy.z; py[3] = vy.w;
                pz[0] = vz.x; pz[1] = vz.y; pz[2] = vz.z; pz[3] = vz.w;
            } else {
#pragma unroll
                for (int j = 0; j < 4; j++) {
                    const int ii = i + j;
                    const bool ok = (ii < N);
                    px[j] = ok ? xs[ii] : 2.0f;
                    py[j] = ok ? ys[ii] : 2.0f;
                    pz[j] = ok ? zs[ii] : 2.0f;
                }
            }
            word = 0;
#pragma unroll
            for (int j = 0; j < 4; j++)
                word |= octant_of(px[j], py[j], pz[j]) << (4 * j);
        }

        // per-thread counts (packed 8-bit x8) + local ranks (2 bits/pt)
        unsigned clo = 0, chi = 0, lrp = 0;
#pragma unroll
        for (int j = 0; j < 4; j++) {
            const unsigned o = (word >> (4 * j)) & 0xFu;
            if (o < 8u) {
                const unsigned sh  = 8u * (o & 3u);
                const unsigned cur = (o < 4u) ? clo : chi;
                lrp |= ((cur >> sh) & 3u) << (2 * j);
                if (o < 4u) clo += 1u << sh; else chi += 1u << sh;
            }
        }

        // warp inclusive scan (packed 8-bit; warp sums <= 128)
        unsigned slo = clo, shi = chi;
#pragma unroll
        for (int d = 1; d < 32; d <<= 1) {
            const unsigned tlo = __shfl_up_sync(0xFFFFFFFFu, slo, d);
            const unsigned thi = __shfl_up_sync(0xFFFFFFFFu, shi, d);
            if (lane >= d) { slo += tlo; shi += thi; }
        }
        if (lane == 31) { sm_ws[w][0] = slo; sm_ws[w][1] = shi; }
        __syncthreads();                                   // (A)

        if (w == 0) {
            const unsigned alo = sm_ws[lane][0], ahi = sm_ws[lane][1];
            unsigned t0 = (alo & 0xFFu)         | (((alo >> 8)  & 0xFFu) << 16);
            unsigned t1 = ((alo >> 16) & 0xFFu) | (((alo >> 24) & 0xFFu) << 16);
            unsigned t2 = (ahi & 0xFFu)         | (((ahi >> 8)  & 0xFFu) << 16);
            unsigned t3 = ((ahi >> 16) & 0xFFu) | (((ahi >> 24) & 0xFFu) << 16);
            const unsigned o0 = t0, o1 = t1, o2 = t2, o3 = t3;
#pragma unroll
            for (int d = 1; d < 32; d <<= 1) {
                const unsigned u0 = __shfl_up_sync(0xFFFFFFFFu, t0, d);
                const unsigned u1 = __shfl_up_sync(0xFFFFFFFFu, t1, d);
                const unsigned u2 = __shfl_up_sync(0xFFFFFFFFu, t2, d);
                const unsigned u3 = __shfl_up_sync(0xFFFFFFFFu, t3, d);
                if (lane >= d) { t0 += u0; t1 += u1; t2 += u2; t3 += u3; }
            }
            sm_off[lane][0] = t0 - o0; sm_off[lane][1] = t1 - o1;
            sm_off[lane][2] = t2 - o2; sm_off[lane][3] = t3 - o3;
            if (lane == 31) {
                sh_totw[0] = t0; sh_totw[1] = t1; sh_totw[2] = t2; sh_totw[3] = t3;
            }
        }
        __syncthreads();                                   // (B)

        const unsigned elo = slo - clo, ehi = shi - chi;   // thread-exclusive
        const unsigned f0 = sm_off[w][0], f1 = sm_off[w][1];
        const unsigned f2 = sm_off[w][2], f3 = sm_off[w][3];
        const unsigned g0 = sh_totw[0], g1 = sh_totw[1];
        const unsigned g2 = sh_totw[2], g3 = sh_totw[3];

        int base[8], tot[8];
        base[0] = sh_gbase[0] + (int)(f0 & 0xFFFFu) + (int)(elo & 0xFFu);
        base[1] = sh_gbase[1] + (int)(f0 >> 16)     + (int)((elo >> 8)  & 0xFFu);
        base[2] = sh_gbase[2] + (int)(f1 & 0xFFFFu) + (int)((elo >> 16) & 0xFFu);
        base[3] = sh_gbase[3] + (int)(f1 >> 16)     + (int)(elo >> 24);
        base[4] = sh_gbase[4] + (int)(f2 & 0xFFFFu) + (int)(ehi & 0xFFu);
        base[5] = sh_gbase[5] + (int)(f2 >> 16)     + (int)((ehi >> 8)  & 0xFFu);
        base[6] = sh_gbase[6] + (int)(f3 & 0xFFFFu) + (int)((ehi >> 16) & 0xFFu);
        base[7] = sh_gbase[7] + (int)(f3 >> 16)     + (int)(ehi >> 24);
        tot[0] = (int)(g0 & 0xFFFFu); tot[1] = (int)(g0 >> 16);
        tot[2] = (int)(g1 & 0xFFFFu); tot[3] = (int)(g1 >> 16);
        tot[4] = (int)(g2 & 0xFFFFu); tot[5] = (int)(g2 >> 16);
        tot[6] = (int)(g3 & 0xFFFFu); tot[7] = (int)(g3 >> 16);

        bool nf = true;
#pragma unroll
        for (int q = 0; q < 8; q++)
            nf = nf && (sh_gbase[q] + tot[q] >= MAX_SAMPLES);
        __syncthreads();                                   // (C)

        if (tid < 8) sh_gbase[tid] += tot[tid];

        // ordered writes (thread order == index order; base = snapshot)
#pragma unroll
        for (int j = 0; j < 4; j++) {
            const unsigned o = (word >> (4 * j)) & 0xFu;
            if (o < 8u) {
                const int rk = base[o] + (int)((lrp >> (2 * j)) & 3u);
                if (rk < MAX_SAMPLES)
                    out_b[((int)o << 9) + rk] = (float)(pbase + tid * 4 + j);
            }
        }

        if (!last || nf) break;    // uniform: only last segment loops (tail)
    }
}

// ---------------------------------------------------------------------------
extern "C" void kernel_launch(void* const* d_in, const int* in_sizes, int n_in,
                              void* d_out, int out_size) {
    const float* pcs = (const float*)d_in[0];
    float* out = (float*)d_out;

    int B = out_size / (8 * MAX_SAMPLES);   // 16
    if (B < 1) B = 1;
    if (B > MAXB) B = MAXB;
    int N = in_sizes[0] / (3 * B);          // 200000

    classify_kernel<<<B * KC, TPB_A>>>(pcs, out, N, B * 8 * MAX_SAMPLES);
    write_kernel<<<B * SEGS, THREADS_B>>>(pcs, out, N);
}

// round 14
// speedup vs baseline: 2.3453x; 1.1171x over previous
#include <cuda_runtime.h>
#include <cstdint>

#define MAX_SAMPLES 512
#define TPB_A 128
#define CHUNK_A 512
#define KC 64                        // chunks per batch window
#define W (KC * CHUNK_A)             // 32768-pt window (fill pt +10.7 sigma)
#define CODES_PER_B (W / 4)          // 8192 ushorts per batch
#define SEGS 8
#define SEG_PTS (W / SEGS)           // 4096
#define CHUNKS_PER_SEG (SEG_PTS / CHUNK_A)   // 8
#define THREADS_B 1024
#define MAXB 64

__device__ unsigned short g_codes[MAXB * CODES_PER_B];   // 1 MB
__device__ int g_counts[MAXB * KC * 8];                  // 128 KB

// Match XLA's non-contracted, left-associated ((x*x)+(y*y))+(z*z).
__device__ __forceinline__ unsigned octant_of(float x, float y, float z) {
    float r2 = __fadd_rn(__fadd_rn(__fmul_rn(x, x), __fmul_rn(y, y)), __fmul_rn(z, z));
    if (!(r2 <= 1.0f)) return 0xFu;
    return ((x >= 0.0f) ? 4u : 0u) | ((y >= 0.0f) ? 2u : 0u) | ((z >= 0.0f) ? 1u : 0u);
}

// ---------------------------------------------------------------------------
// Pass 1 (wide): classify window points -> 4-bit codes, per-chunk octant
// counts, and blanket -1 output fill. 1024 blocks for 16 batches.
// ---------------------------------------------------------------------------
__global__ void classify_kernel(const float* __restrict__ pcs, float* __restrict__ out,
                                int N, int out_count) {
    const int b   = blockIdx.x >> 6;      // / KC
    const int k   = blockIdx.x & (KC - 1);
    const int tid = threadIdx.x;

    const int fidx = blockIdx.x * TPB_A + tid;   // grid covers 2x out_count
    if (fidx < out_count) out[fidx] = -1.0f;

    const int i0 = k * CHUNK_A + tid * 4;
    unsigned word = 0xFFFFu;              // all-invalid (pad)
    if (i0 < N) {
        const float* __restrict__ xs = pcs + (size_t)b * 3 * N;
        const float* __restrict__ ys = xs + N;
        const float* __restrict__ zs = ys + N;
        float px[4], py[4], pz[4];
        if (i0 + 3 < N && (N & 3) == 0) {
            const float4 vx = *reinterpret_cast<const float4*>(xs + i0);
            const float4 vy = *reinterpret_cast<const float4*>(ys + i0);
            const float4 vz = *reinterpret_cast<const float4*>(zs + i0);
            px[0] = vx.x; px[1] = vx.y; px[2] = vx.z; px[3] = vx.w;
            py[0] = vy.x; py[1] = vy.y; py[2] = vy.z; py[3] = vy.w;
            pz[0] = vz.x; pz[1] = vz.y; pz[2] = vz.z; pz[3] = vz.w;
        } else {
#pragma unroll
            for (int j = 0; j < 4; j++) {
                const int ii = i0 + j;
                const bool ok = (ii < N);
                px[j] = ok ? xs[ii] : 2.0f;   // sentinel: outside ball
                py[j] = ok ? ys[ii] : 2.0f;
                pz[j] = ok ? zs[ii] : 2.0f;
            }
        }
        word = 0;
#pragma unroll
        for (int j = 0; j < 4; j++)
            word |= octant_of(px[j], py[j], pz[j]) << (4 * j);
    }
    g_codes[b * CODES_PER_B + (i0 >> 2)] = (unsigned short)word;

    // per-chunk counts (packed bytes -> warp reduce -> 4-warp combine)
    unsigned clo = 0, chi = 0;
#pragma unroll
    for (int j = 0; j < 4; j++) {
        const unsigned o = (word >> (4 * j)) & 0xFu;
        if (o < 8u) { if (o < 4u) clo += 1u << (8 * o); else chi += 1u << (8 * (o - 4)); }
    }
#pragma unroll
    for (int off = 16; off > 0; off >>= 1) {
        clo += __shfl_down_sync(0xFFFFFFFFu, clo, off);
        chi += __shfl_down_sync(0xFFFFFFFFu, chi, off);
    }
    __shared__ unsigned smc[4][2];
    if ((tid & 31) == 0) { smc[tid >> 5][0] = clo; smc[tid >> 5][1] = chi; }
    __syncthreads();
    if (tid < 8) {
        int v = 0;
#pragma unroll
        for (int w2 = 0; w2 < 4; w2++) {
            const unsigned c = (tid < 4) ? smc[w2][0] : smc[w2][1];
            v += (int)((c >> (8 * (tid & 3))) & 0xFFu);
        }
        g_counts[((size_t)b * KC + k) * 8 + tid] = v;
    }
}

// ---------------------------------------------------------------------------
// Pass 2 (wide): one block per 4096-pt segment. Bases now computed by a
// PARALLEL warp-per-octant reduction (R13 post-mortem: the tid<8 serial
// 56-load chain cost ~13k cycles = the entire kernel duration).
// ---------------------------------------------------------------------------
__global__ __launch_bounds__(THREADS_B, 1)
void write_kernel(const float* __restrict__ pcs, float* __restrict__ out, int N) {
    const int b    = blockIdx.x / SEGS;
    const int seg  = blockIdx.x % SEGS;
    const int tid  = threadIdx.x;
    const int lane = tid & 31;
    const int w    = tid >> 5;

    __shared__ unsigned sm_ws[32][2];
    __shared__ unsigned sm_off[32][4];
    __shared__ unsigned sh_totw[4];
    __shared__ int sh_gbase[8];

    // Parallel base reduction: warp w (<8) owns octant w; lanes cover chunks
    // stride-32 (kend <= 56 -> at most 2 independent loads per lane).
    const int kend = seg * CHUNKS_PER_SEG;
    if (w < 8) {
        int v = 0;
        for (int kk = lane; kk < kend; kk += 32)
            v += g_counts[((size_t)b * KC + kk) * 8 + w];
#pragma unroll
        for (int off = 16; off > 0; off >>= 1)
            v += __shfl_down_sync(0xFFFFFFFFu, v, off);
        if (lane == 0) sh_gbase[w] = v;
    }
    __syncthreads();

    {
        bool full = true;
#pragma unroll
        for (int q = 0; q < 8; q++) full = full && (sh_gbase[q] >= MAX_SAMPLES);
        if (full) return;                 // uniform; no code/point reads
    }

    const float* __restrict__ xs = pcs + (size_t)b * 3 * N;
    const float* __restrict__ ys = xs + N;
    const float* __restrict__ zs = ys + N;
    float* __restrict__ out_b = out + (size_t)b * (8 * MAX_SAMPLES);
    const unsigned short* __restrict__ cp = g_codes + b * CODES_PER_B;

    const bool last = (seg == SEGS - 1);

    for (int iter = 0; ; iter++) {
        int pbase;
        unsigned word;
        if (iter == 0) {
            pbase = seg * SEG_PTS;
            word = cp[seg * (SEG_PTS / 4) + tid];
        } else {
            pbase = W + (iter - 1) * SEG_PTS;        // raw tail (last block only)
            if (pbase >= N) break;
            const int i = pbase + tid * 4;
            float px[4], py[4], pz[4];
            if (i + 3 < N && (N & 3) == 0) {
                const float4 vx = *reinterpret_cast<const float4*>(xs + i);
                const float4 vy = *reinterpret_cast<const float4*>(ys + i);
                const float4 vz = *reinterpret_cast<const float4*>(zs + i);
                px[0] = vx.x; px[1] = vx.y; px[2] = vx.z; px[3] = vx.w;
                py[0] = vy.x; py[1] = vy.y; py[2] = vy.z; py[3] = vy.w;
                pz[0] = vz.x; pz[1] = vz.y; pz[2] = vz.z; pz[3] = vz.w;
            } else {
#pragma unroll
                for (int j = 0; j < 4; j++) {
                    const int ii = i + j;
                    const bool ok = (ii < N);
                    px[j] = ok ? xs[ii] : 2.0f;
                    py[j] = ok ? ys[ii] : 2.0f;
                    pz[j] = ok ? zs[ii] : 2.0f;
                }
            }
            word = 0;
#pragma unroll
            for (int j = 0; j < 4; j++)
                word |= octant_of(px[j], py[j], pz[j]) << (4 * j);
        }

        // per-thread counts (packed 8-bit x8) + local ranks (2 bits/pt)
        unsigned clo = 0, chi = 0, lrp = 0;
#pragma unroll
        for (int j = 0; j < 4; j++) {
            const unsigned o = (word >> (4 * j)) & 0xFu;
            if (o < 8u) {
                const unsigned sh  = 8u * (o & 3u);
                const unsigned cur = (o < 4u) ? clo : chi;
                lrp |= ((cur >> sh) & 3u) << (2 * j);
                if (o < 4u) clo += 1u << sh; else chi += 1u << sh;
            }
        }

        // warp inclusive scan (packed 8-bit; warp sums <= 128)
        unsigned slo = clo, shi = chi;
#pragma unroll
        for (int d = 1; d < 32; d <<= 1) {
            const unsigned tlo = __shfl_up_sync(0xFFFFFFFFu, slo, d);
            const unsigned thi = __shfl_up_sync(0xFFFFFFFFu, shi, d);
            if (lane >= d) { slo += tlo; shi += thi; }
        }
        if (lane == 31) { sm_ws[w][0] = slo; sm_ws[w][1] = shi; }
        __syncthreads();                                   // (A)

        if (w == 0) {
            const unsigned alo = sm_ws[lane][0], ahi = sm_ws[lane][1];
            unsigned t0 = (alo & 0xFFu)         | (((alo >> 8)  & 0xFFu) << 16);
            unsigned t1 = ((alo >> 16) & 0xFFu) | (((alo >> 24) & 0xFFu) << 16);
            unsigned t2 = (ahi & 0xFFu)         | (((ahi >> 8)  & 0xFFu) << 16);
            unsigned t3 = ((ahi >> 16) & 0xFFu) | (((ahi >> 24) & 0xFFu) << 16);
            const unsigned o0 = t0, o1 = t1, o2 = t2, o3 = t3;
#pragma unroll
            for (int d = 1; d < 32; d <<= 1) {
                const unsigned u0 = __shfl_up_sync(0xFFFFFFFFu, t0, d);
                const unsigned u1 = __shfl_up_sync(0xFFFFFFFFu, t1, d);
                const unsigned u2 = __shfl_up_sync(0xFFFFFFFFu, t2, d);
                const unsigned u3 = __shfl_up_sync(0xFFFFFFFFu, t3, d);
                if (lane >= d) { t0 += u0; t1 += u1; t2 += u2; t3 += u3; }
            }
            sm_off[lane][0] = t0 - o0; sm_off[lane][1] = t1 - o1;
            sm_off[lane][2] = t2 - o2; sm_off[lane][3] = t3 - o3;
            if (lane == 31) {
                sh_totw[0] = t0; sh_totw[1] = t1; sh_totw[2] = t2; sh_totw[3] = t3;
            }
        }
        __syncthreads();                                   // (B)

        const unsigned elo = slo - clo, ehi = shi - chi;   // thread-exclusive
        const unsigned f0 = sm_off[w][0], f1 = sm_off[w][1];
        const unsigned f2 = sm_off[w][2], f3 = sm_off[w][3];
        const unsigned g0 = sh_totw[0], g1 = sh_totw[1];
        const unsigned g2 = sh_totw[2], g3 = sh_totw[3];

        int base[8], tot[8];
        base[0] = sh_gbase[0] + (int)(f0 & 0xFFFFu) + (int)(elo & 0xFFu);
        base[1] = sh_gbase[1] + (int)(f0 >> 16)     + (int)((elo >> 8)  & 0xFFu);
        base[2] = sh_gbase[2] + (int)(f1 & 0xFFFFu) + (int)((elo >> 16) & 0xFFu);
        base[3] = sh_gbase[3] + (int)(f1 >> 16)     + (int)(elo >> 24);
        base[4] = sh_gbase[4] + (int)(f2 & 0xFFFFu) + (int)(ehi & 0xFFu);
        base[5] = sh_gbase[5] + (int)(f2 >> 16)     + (int)((ehi >> 8)  & 0xFFu);
        base[6] = sh_gbase[6] + (int)(f3 & 0xFFFFu) + (int)((ehi >> 16) & 0xFFu);
        base[7] = sh_gbase[7] + (int)(f3 >> 16)     + (int)(ehi >> 24);
        tot[0] = (int)(g0 & 0xFFFFu); tot[1] = (int)(g0 >> 16);
        tot[2] = (int)(g1 & 0xFFFFu); tot[3] = (int)(g1 >> 16);
        tot[4] = (int)(g2 & 0xFFFFu); tot[5] = (int)(g2 >> 16);
        tot[6] = (int)(g3 & 0xFFFFu); tot[7] = (int)(g3 >> 16);

        bool nf = true;
#pragma unroll
        for (int q = 0; q < 8; q++)
            nf = nf && (sh_gbase[q] + tot[q] >= MAX_SAMPLES);
        __syncthreads();                                   // (C)

        if (tid < 8) sh_gbase[tid] += tot[tid];

        // ordered writes (thread order == index order; base = snapshot)
#pragma unroll
        for (int j = 0; j < 4; j++) {
            const unsigned o = (word >> (4 * j)) & 0xFu;
            if (o < 8u) {
                const int rk = base[o] + (int)((lrp >> (2 * j)) & 3u);
                if (rk < MAX_SAMPLES)
                    out_b[((int)o << 9) + rk] = (float)(pbase + tid * 4 + j);
            }
        }

        if (!last || nf) break;    // uniform: only last segment loops (tail)
    }
}

// ---------------------------------------------------------------------------
extern "C" void kernel_launch(void* const* d_in, const int* in_sizes, int n_in,
                              void* d_out, int out_size) {
    const float* pcs = (const float*)d_in[0];
    float* out = (float*)d_out;

    int B = out_size / (8 * MAX_SAMPLES);   // 16
    if (B < 1) B = 1;
    if (B > MAXB) B = MAXB;
    int N = in_sizes[0] / (3 * B);          // 200000

    classify_kernel<<<B * KC, TPB_A>>>(pcs, out, N, B * 8 * MAX_SAMPLES);
    write_kernel<<<B * SEGS, THREADS_B>>>(pcs, out, N);
}